// round 15
// baseline (speedup 1.0000x reference)
#include <cuda_runtime.h>
#include <cuda_bf16.h>

#define NUM_CLASSES 1000
#define FEAT_DIM    512
#define BATCH       65536
#define NBLK        16      // count-kernel blocks / partial histograms
#define GRID_D      1024    // dist blocks
#define SPW         8       // samples per warp (65536 / (1024*8 warps))

// Stateless scratch: fully overwritten by every invocation (plain stores),
// no fences anywhere (.gpu-scope fences flush L1D -> measured regression).
__device__ int   g_part[NUM_CLASSES * NBLK];
__device__ float g_inv[NUM_CLASSES];

// Launch 1: per-block smem histogram, plain-stored partials. ZERO global atomics.
__global__ __launch_bounds__(1024) void count_kernel(
    const long long* __restrict__ labels, float* __restrict__ out)
{
    __shared__ int h[NUM_CLASSES];
    for (int j = threadIdx.x; j < NUM_CLASSES; j += 1024)
        h[j] = 0;
    if (blockIdx.x == 0 && threadIdx.x == 0)
        out[0] = 0.0f;
    __syncthreads();

    const int base = blockIdx.x * (BATCH / NBLK);
#pragma unroll
    for (int k = 0; k < BATCH / NBLK / 1024; k++) {
        int l = (int)labels[base + k * 1024 + threadIdx.x];
        atomicAdd_block(&h[l], 1);
    }
    __syncthreads();

    for (int j = threadIdx.x; j < NUM_CLASSES; j += 1024)
        g_part[j * NBLK + blockIdx.x] = h[j];
}

// Launch 2: fold partials into the per-class inverse weight (4 KB table).
__global__ __launch_bounds__(1024) void inv_kernel()
{
    int j = threadIdx.x;
    if (j < NUM_CLASSES) {
        int c = 0;
#pragma unroll
        for (int b = 0; b < NBLK; b++)
            c += g_part[j * NBLK + b];
        g_inv[j] = (c > 0)
            ? 1.0f / ((float)c * ((float)FEAT_DIM * (float)BATCH))
            : 0.0f;
    }
}

// Launch 3: persistent warps — each warp handles SPW samples (stride 8192).
// Loop body: 8 float4 loads + inv broadcast + 16 FMAs + 1 weighted FMA per
// lane. NO shuffles / smem / atomics inside the loop; one warp+block reduce
// and ONE single-address atomic per block at the end (1024 total).
__global__ __launch_bounds__(256, 4) void dist_kernel(
    const float4* __restrict__ feat,
    const float4* __restrict__ cent,
    const long long* __restrict__ labels,
    float* __restrict__ out)
{
    const int lane = threadIdx.x & 31;
    const int wid  = threadIdx.x >> 5;
    const int wg   = blockIdx.x * 8 + wid;     // 0..8191

    float vacc = 0.0f;

#pragma unroll
    for (int k = 0; k < SPW; k++) {
        const int sample = wg + k * (GRID_D * 8);
        const int lbl = (int)labels[sample];             // broadcast

        const float4* fr = feat + (size_t)sample * (FEAT_DIM / 4);
        const float4* cr = cent + (size_t)lbl    * (FEAT_DIM / 4);

        float4 a0 = fr[lane];
        float4 a1 = fr[lane + 32];
        float4 a2 = fr[lane + 64];
        float4 a3 = fr[lane + 96];
        float4 b0 = cr[lane];
        float4 b1 = cr[lane + 32];
        float4 b2 = cr[lane + 64];
        float4 b3 = cr[lane + 96];

        const float w = g_inv[lbl];                      // L1-hot 4 KB table

        float acc = 0.0f, d;
        d = a0.x - b0.x; acc = fmaf(d, d, acc);
        d = a0.y - b0.y; acc = fmaf(d, d, acc);
        d = a0.z - b0.z; acc = fmaf(d, d, acc);
        d = a0.w - b0.w; acc = fmaf(d, d, acc);
        d = a1.x - b1.x; acc = fmaf(d, d, acc);
        d = a1.y - b1.y; acc = fmaf(d, d, acc);
        d = a1.z - b1.z; acc = fmaf(d, d, acc);
        d = a1.w - b1.w; acc = fmaf(d, d, acc);
        d = a2.x - b2.x; acc = fmaf(d, d, acc);
        d = a2.y - b2.y; acc = fmaf(d, d, acc);
        d = a2.z - b2.z; acc = fmaf(d, d, acc);
        d = a2.w - b2.w; acc = fmaf(d, d, acc);
        d = a3.x - b3.x; acc = fmaf(d, d, acc);
        d = a3.y - b3.y; acc = fmaf(d, d, acc);
        d = a3.z - b3.z; acc = fmaf(d, d, acc);
        d = a3.w - b3.w; acc = fmaf(d, d, acc);

        vacc = fmaf(acc, w, vacc);    // weight uniform per sample -> exact
    }

    // one warp reduce at the end
#pragma unroll
    for (int off = 16; off > 0; off >>= 1)
        vacc += __shfl_xor_sync(0xFFFFFFFFu, vacc, off);

    __shared__ float s[8];
    if (lane == 0) s[wid] = vacc;
    __syncthreads();

    if (threadIdx.x == 0) {
        float t = 0.0f;
#pragma unroll
        for (int w2 = 0; w2 < 8; w2++) t += s[w2];
        atomicAdd(out, t);            // single address, 1024 total
    }
}

extern "C" void kernel_launch(void* const* d_in, const int* in_sizes, int n_in,
                              void* d_out, int out_size) {
    const float4*    feat   = (const float4*)d_in[0];
    const float4*    cent   = (const float4*)d_in[1];
    const long long* labels = (const long long*)d_in[2];
    float* out = (float*)d_out;

    count_kernel<<<NBLK, 1024>>>(labels, out);
    inv_kernel<<<1, 1024>>>();
    dist_kernel<<<GRID_D, 256>>>(feat, cent, labels, out);
}